// round 14
// baseline (speedup 1.0000x reference)
#include <cuda_runtime.h>
#include <math.h>
#include <stdint.h>

#define D 64
#define MAXN 50000
#define MAXE 800000
#define TR 128   // rows per GEMM tile

// ---------------- scratch (device globals) ----------------------------------
__device__ float  g_es[MAXN * D];
__device__ float  g_ed[MAXN * D];
__device__ float  g_Bh[MAXN * D];
__device__ float  g_feat[MAXN * D];
__device__ float  g_el[MAXN * 2];
__device__ float  g_er[MAXN * 2];
__device__ float  g_xpre[MAXN * D];
__device__ float  g_m[(size_t)MAXE * D];
__device__ int    g_deg[MAXN];
__device__ int    g_off[MAXN + 1];
__device__ int    g_cur[MAXN];
__device__ int    g_eid[MAXE];
__device__ int    g_bsum[256];
__device__ float  g_Wcomb[D * D];
__device__ float  g_bcomb[D];
__device__ double g_esum[D], g_esq[D], g_nsum[D], g_nsq[D];
__device__ float  g_bea[D], g_beb[D], g_bna[D], g_bnb[D];

// ---------------- f32x2 helpers ---------------------------------------------
__device__ __forceinline__ unsigned long long dup2(float x) {
    unsigned long long r;
    asm("mov.b64 %0, {%1, %1};" : "=l"(r) : "f"(x));
    return r;
}
__device__ __forceinline__ void ffma2(unsigned long long& d, unsigned long long a,
                                      unsigned long long b) {
    asm("fma.rn.f32x2 %0, %1, %2, %0;" : "+l"(d) : "l"(a), "l"(b));
}
__device__ __forceinline__ float2 unpack2(unsigned long long v) {
    float2 f;
    asm("mov.b64 {%0, %1}, %2;" : "=f"(f.x), "=f"(f.y) : "l"(v));
    return f;
}
__device__ __forceinline__ float to_tf32(float v) {
    uint32_t t;
    asm("cvt.rna.tf32.f32 %0, %1;" : "=r"(t) : "f"(v));
    return __uint_as_float(t);
}
__device__ __forceinline__ void mma_tf32(float& c0, float& c1, float& c2, float& c3,
                                         uint32_t a0, uint32_t a1, uint32_t a2, uint32_t a3,
                                         uint32_t b0, uint32_t b1) {
    asm volatile(
        "mma.sync.aligned.m16n8k8.row.col.f32.tf32.tf32.f32 "
        "{%0,%1,%2,%3}, {%4,%5,%6,%7}, {%8,%9}, {%0,%1,%2,%3};"
        : "+f"(c0), "+f"(c1), "+f"(c2), "+f"(c3)
        : "r"(a0), "r"(a1), "r"(a2), "r"(a3), "r"(b0), "r"(b1));
}

// ---------------- init ------------------------------------------------------
__global__ void k_init(int Nn) {
    int i = blockIdx.x * blockDim.x + threadIdx.x;
    if (i < Nn) g_deg[i] = 0;
    if (i < D) { g_esum[i] = 0.0; g_esq[i] = 0.0; g_nsum[i] = 0.0; g_nsq[i] = 0.0; }
}

__global__ void k_wcomb(const float* __restrict__ Wsu, const float* __restrict__ bsu,
                        const float* __restrict__ Wgat) {
    int idx = blockIdx.x * blockDim.x + threadIdx.x;
    for (int i = idx; i < D * D; i += gridDim.x * blockDim.x) {
        int k = i >> 6, j = i & 63;
        float s = 0.f;
        for (int t = 0; t < D; t++) s = fmaf(Wsu[k * D + t], Wgat[t * D + j], s);
        g_Wcomb[i] = s;
    }
    if (idx < D) {
        float s = 0.f;
        for (int t = 0; t < D; t++) s = fmaf(bsu[t], Wgat[t * D + idx], s);
        g_bcomb[idx] = s;
    }
}

// ---------------- CSR build -------------------------------------------------
__global__ void k_deg(const int* __restrict__ dst, int E) {
    int e = blockIdx.x * blockDim.x + threadIdx.x;
    if (e < E) atomicAdd(&g_deg[dst[e]], 1);
}

__global__ void k_scan1(int n) {
    __shared__ int s[512];
    int i = blockIdx.x * 512 + threadIdx.x;
    int v = (i < n) ? g_deg[i] : 0;
    s[threadIdx.x] = v;
    __syncthreads();
    for (int o = 1; o < 512; o <<= 1) {
        int t = (threadIdx.x >= o) ? s[threadIdx.x - o] : 0;
        __syncthreads();
        s[threadIdx.x] += t;
        __syncthreads();
    }
    if (i < n) g_off[i + 1] = s[threadIdx.x];
    if (threadIdx.x == 511) g_bsum[blockIdx.x] = s[511];
}

__global__ void k_scan2(int B) {
    __shared__ int s[128];
    int v = (threadIdx.x < B) ? g_bsum[threadIdx.x] : 0;
    s[threadIdx.x] = v;
    __syncthreads();
    for (int o = 1; o < 128; o <<= 1) {
        int t = (threadIdx.x >= o) ? s[threadIdx.x - o] : 0;
        __syncthreads();
        s[threadIdx.x] += t;
        __syncthreads();
    }
    if (threadIdx.x < B) g_bsum[threadIdx.x] = s[threadIdx.x] - v;
}

__global__ void k_scan3(int n) {
    int i = blockIdx.x * blockDim.x + threadIdx.x;
    if (i < n) {
        int inc = g_off[i + 1] + g_bsum[i >> 9];
        g_off[i + 1] = inc;
        g_cur[i] = inc - g_deg[i];
    }
    if (i == 0) g_off[0] = 0;
}

__global__ void k_fill(const int* __restrict__ dst, int E) {
    int e = blockIdx.x * blockDim.x + threadIdx.x;
    if (e < E) {
        int p = atomicAdd(&g_cur[dst[e]], 1);
        g_eid[p] = e;
    }
}

// ---------------- node GEMMs (4 matrices, 8x4 f32x2 blocking — R6 shape) -----
__global__ __launch_bounds__(256) void k_node(
    const float* __restrict__ X,
    const float* __restrict__ Wsg, const float* __restrict__ bsg,
    const float* __restrict__ Wdg, const float* __restrict__ bdg,
    const float* __restrict__ Wdu, const float* __restrict__ bdu, int Nn) {
    __shared__ float Xs[D][TR + 4];
    __shared__ float Ws[D][68];
    int tid = threadIdx.x;
    int r0 = blockIdx.x * TR;
    for (int i = tid; i < TR * D; i += 256) {
        int r = i >> 6, k = i & 63;
        int gr = r0 + r;
        Xs[k][r] = (gr < Nn) ? X[(size_t)gr * D + k] : 0.f;
    }
    int tx = tid & 15, ty = tid >> 4;
    int cc = tx * 4, rr = ty * 8;
    const float* Wp[4] = {Wsg, Wdg, Wdu, g_Wcomb};
    const float* bp[4] = {bsg, bdg, bdu, g_bcomb};
    float* op[4] = {g_es, g_ed, g_Bh, g_feat};
    for (int mm = 0; mm < 4; mm++) {
        __syncthreads();
        for (int i = tid; i < D * D; i += 256) Ws[i >> 6][i & 63] = Wp[mm][i];
        __syncthreads();
        unsigned long long acc[4][4];
        #pragma unroll
        for (int p = 0; p < 4; p++)
            #pragma unroll
            for (int j = 0; j < 4; j++) acc[p][j] = 0ull;
        #pragma unroll 8
        for (int k = 0; k < D; k++) {
            ulonglong2 a01 = *(const ulonglong2*)&Xs[k][rr];
            ulonglong2 a23 = *(const ulonglong2*)&Xs[k][rr + 4];
            float4 b4 = *(const float4*)&Ws[k][cc];
            unsigned long long bd[4] = {dup2(b4.x), dup2(b4.y), dup2(b4.z), dup2(b4.w)};
            unsigned long long av[4] = {a01.x, a01.y, a23.x, a23.y};
            #pragma unroll
            for (int p = 0; p < 4; p++)
                #pragma unroll
                for (int j = 0; j < 4; j++) ffma2(acc[p][j], av[p], bd[j]);
        }
        float bias[4];
        *(float4*)bias = *(const float4*)&bp[mm][cc];
        #pragma unroll
        for (int p = 0; p < 4; p++) {
            float2 u[4];
            #pragma unroll
            for (int j = 0; j < 4; j++) u[j] = unpack2(acc[p][j]);
            int row0 = r0 + rr + 2 * p;
            if (row0 < Nn)
                *(float4*)&op[mm][(size_t)row0 * D + cc] =
                    make_float4(u[0].x + bias[0], u[1].x + bias[1],
                                u[2].x + bias[2], u[3].x + bias[3]);
            if (row0 + 1 < Nn)
                *(float4*)&op[mm][(size_t)(row0 + 1) * D + cc] =
                    make_float4(u[0].y + bias[0], u[1].y + bias[1],
                                u[2].y + bias[2], u[3].y + bias[3]);
        }
    }
}

// ---------------- attention logits from g_feat ------------------------------
__global__ void k_attn(const float* __restrict__ attl, const float* __restrict__ attr, int Nn) {
    int w = (blockIdx.x * blockDim.x + threadIdx.x) >> 5;
    int lane = threadIdx.x & 31;
    if (w >= Nn) return;
    float2 f = *(const float2*)&g_feat[(size_t)w * D + 2 * lane];
    float2 al = *(const float2*)&attl[2 * lane];
    float2 ar = *(const float2*)&attr[2 * lane];
    float pl = fmaf(f.x, al.x, f.y * al.y);
    float pr = fmaf(f.x, ar.x, f.y * ar.y);
    #pragma unroll
    for (int o = 8; o; o >>= 1) {
        pl += __shfl_xor_sync(0xffffffffu, pl, o);
        pr += __shfl_xor_sync(0xffffffffu, pr, o);
    }
    if ((lane & 15) == 0) {
        int h = lane >> 4;
        g_el[2 * w + h] = pl;
        g_er[2 * w + h] = pr;
    }
}

// ---------------- edge GEMM via tf32 mma.sync + m + BN-edge stats ------------
// warp = 8-col strip, B fragments held in registers; A streamed from smem.
__global__ __launch_bounds__(256) void k_edge(
    const float* __restrict__ EF, const float* __restrict__ Weg,
    const float* __restrict__ beg, const int* __restrict__ src,
    const int* __restrict__ dst, int E) {
    __shared__ float As[TR][68];   // [row][k], tf32-converted, stride 68 (conflict-free)
    __shared__ float Bt[D][68];    // [n][k],   tf32-converted
    __shared__ int ssrc[TR], sdst[TR];
    __shared__ float sb[D];
    __shared__ float ssum[D], ssq[D];
    int tid = threadIdx.x;
    int lane = tid & 31, wid = tid >> 5;
    int gid = lane >> 2, tig = lane & 3;
    int r0b = blockIdx.x * TR;
    for (int i = tid; i < TR * D; i += 256) {
        int r = i >> 6, k = i & 63;
        int e = r0b + r;
        As[r][k] = (e < E) ? to_tf32(EF[(size_t)e * D + k]) : 0.f;
    }
    for (int i = tid; i < D * D; i += 256) {
        int k = i >> 6, n = i & 63;
        Bt[n][k] = to_tf32(Weg[i]);
    }
    for (int i = tid; i < TR; i += 256) {
        int e = r0b + i;
        ssrc[i] = (e < E) ? src[e] : 0;
        sdst[i] = (e < E) ? dst[e] : 0;
    }
    if (tid < D) {
        sb[tid] = beg[tid];
        ssum[tid] = 0.f;
        ssq[tid] = 0.f;
    }
    __syncthreads();
    int n0 = wid * 8;
    // preload B fragments (held for the whole block): b0=(k=tig, n=gid), b1=(k=tig+4)
    uint32_t bfr[8][2];
    #pragma unroll
    for (int ks = 0; ks < 8; ks++) {
        bfr[ks][0] = __float_as_uint(Bt[n0 + gid][ks * 8 + tig]);
        bfr[ks][1] = __float_as_uint(Bt[n0 + gid][ks * 8 + tig + 4]);
    }
    int cp = n0 + 2 * tig;           // this thread's column pair
    float2 bias2 = *(const float2*)&sb[cp];
    float cs0 = 0.f, cs1 = 0.f, cq0 = 0.f, cq1 = 0.f;
    #pragma unroll
    for (int rt = 0; rt < 8; rt++) {
        int r0 = rt * 16;
        float c0 = 0.f, c1 = 0.f, c2 = 0.f, c3 = 0.f;
        #pragma unroll
        for (int ks = 0; ks < 8; ks++) {
            int kk = ks * 8;
            uint32_t a0 = __float_as_uint(As[r0 + gid][kk + tig]);
            uint32_t a1 = __float_as_uint(As[r0 + gid + 8][kk + tig]);
            uint32_t a2 = __float_as_uint(As[r0 + gid][kk + tig + 4]);
            uint32_t a3 = __float_as_uint(As[r0 + gid + 8][kk + tig + 4]);
            mma_tf32(c0, c1, c2, c3, a0, a1, a2, a3, bfr[ks][0], bfr[ks][1]);
        }
        // epilogue: rows ra (c0,c1) and rb (c2,c3), cols cp, cp+1
        #pragma unroll
        for (int hh = 0; hh < 2; hh++) {
            int rl = r0 + gid + hh * 8;
            int e = r0b + rl;
            if (e < E) {
                int s = ssrc[rl], d = sdst[rl];
                float2 es2 = *(const float2*)&g_es[(size_t)s * D + cp];
                float2 ed2 = *(const float2*)&g_ed[(size_t)d * D + cp];
                float m0 = (hh ? c2 : c0) + bias2.x + es2.x + ed2.x;
                float m1 = (hh ? c3 : c1) + bias2.y + es2.y + ed2.y;
                *(float2*)&g_m[(size_t)e * D + cp] = make_float2(m0, m1);
                cs0 += m0; cs1 += m1;
                cq0 = fmaf(m0, m0, cq0);
                cq1 = fmaf(m1, m1, cq1);
            }
        }
    }
    // reduce stats across gid (lanes sharing tig): offsets 4, 8, 16
    #pragma unroll
    for (int o = 4; o <= 16; o <<= 1) {
        cs0 += __shfl_xor_sync(0xffffffffu, cs0, o);
        cs1 += __shfl_xor_sync(0xffffffffu, cs1, o);
        cq0 += __shfl_xor_sync(0xffffffffu, cq0, o);
        cq1 += __shfl_xor_sync(0xffffffffu, cq1, o);
    }
    if (gid == 0) {
        atomicAdd(&ssum[cp], cs0);
        atomicAdd(&ssum[cp + 1], cs1);
        atomicAdd(&ssq[cp], cq0);
        atomicAdd(&ssq[cp + 1], cq1);
    }
    __syncthreads();
    if (tid < D) {
        atomicAdd(&g_esum[tid], (double)ssum[tid]);
        atomicAdd(&g_esq[tid], (double)ssq[tid]);
    }
}

// ---------------- edge-BN scale/shift prep (before gather) -------------------
__global__ void k_bnprep_e(const float* __restrict__ ge, const float* __restrict__ be, int E) {
    int c = threadIdx.x;
    if (c < D) {
        double me = g_esum[c] / (double)E;
        double ve = g_esq[c] / (double)E - me * me;
        double rse = 1.0 / sqrt(ve + 1e-5);
        g_bea[c] = (float)(rse)*ge[c];
        g_beb[c] = be[c] - (float)(me * rse) * ge[c];
    }
}

// ---------------- gather aggregation + fused y output (R9 champion form) -----
__global__ void k_gather(const int* __restrict__ src, const float* __restrict__ bgat,
                         const float* __restrict__ ef, float* __restrict__ y, int Nn) {
    int w = (blockIdx.x * blockDim.x + threadIdx.x) >> 5;
    int lane = threadIdx.x & 31;
    if (w >= Nn) return;
    int off = g_off[w];
    int deg = g_off[w + 1] - off;
    float er0 = g_er[w * 2], er1 = g_er[w * 2 + 1];
    int c0 = lane, c1 = lane + 32;
    float bea0 = g_bea[c0], bea1 = g_bea[c1];
    float beb0 = g_beb[c0], beb1 = g_beb[c1];
    float num0 = 0, num1 = 0, den0 = 0, den1 = 0;
    float ga0 = 0, ga1 = 0, exs0 = 0, exs1 = 0;
    for (int base = 0; base < deg; base += 32) {
        int n = min(32, deg - base);
        int el = 0, sl = 0;
        float lex0 = 0.f, lex1 = 0.f;
        if (lane < n) {
            el = g_eid[off + base + lane];
            sl = src[el];
            float l0 = g_el[2 * sl] + er0;     l0 = l0 > 0.f ? l0 : 0.2f * l0;
            float l1 = g_el[2 * sl + 1] + er1; l1 = l1 > 0.f ? l1 : 0.2f * l1;
            lex0 = __expf(l0);
            lex1 = __expf(l1);
        }
        #pragma unroll 4
        for (int j = 0; j < n; j++) {
            int ej = __shfl_sync(0xffffffffu, el, j);
            int sj = __shfl_sync(0xffffffffu, sl, j);
            float x0 = __shfl_sync(0xffffffffu, lex0, j);
            float x1 = __shfl_sync(0xffffffffu, lex1, j);
            size_t mb = (size_t)ej * D;
            size_t sb = (size_t)sj * D;
            float m0 = g_m[mb + c0], m1 = g_m[mb + c1];
            float e0 = ef[mb + c0], e1 = ef[mb + c1];
            float bh0 = g_Bh[sb + c0], bh1 = g_Bh[sb + c1];
            float f0 = g_feat[sb + c0], f1 = g_feat[sb + c1];
            float sg0 = 1.f / (1.f + __expf(-m0));
            float sg1 = 1.f / (1.f + __expf(-m1));
            num0 = fmaf(sg0, bh0, num0);
            num1 = fmaf(sg1, bh1, num1);
            den0 += sg0;
            den1 += sg1;
            ga0 = fmaf(x0, f0, ga0);
            ga1 = fmaf(x1, f1, ga1);
            exs0 += x0;
            exs1 += x1;
            float t0 = fmaf(m0, bea0, beb0);
            float t1 = fmaf(m1, bea1, beb1);
            y[mb + c0] = e0 + t0 / (1.f + __expf(-t0));
            y[mb + c1] = e1 + t1 / (1.f + __expf(-t1));
        }
    }
    float h0 = num0 / (den0 + 1e-6f);
    float h1 = num1 / (den1 + 1e-6f);
    float gg0 = deg ? ga0 / exs0 : 0.f;
    float gg1 = deg ? ga1 / exs1 : 0.f;
    g_xpre[(size_t)w * D + c0] = h0 + gg0 + bgat[c0];
    g_xpre[(size_t)w * D + c1] = h1 + gg1 + bgat[c1];
}

// ---------------- node BN stats over x_pre ----------------------------------
__global__ void k_nstats(int Nn) {
    int c = threadIdx.x & 63;
    int g = threadIdx.x >> 6;
    float s = 0.f, q = 0.f;
    for (int r = blockIdx.x * 4 + g; r < Nn; r += gridDim.x * 4) {
        float v = g_xpre[(size_t)r * D + c];
        s += v;
        q = fmaf(v, v, q);
    }
    __shared__ float sh[256], shq[256];
    sh[threadIdx.x] = s;
    shq[threadIdx.x] = q;
    __syncthreads();
    if (g == 0) {
        s = sh[c] + sh[c + 64] + sh[c + 128] + sh[c + 192];
        q = shq[c] + shq[c + 64] + shq[c + 128] + shq[c + 192];
        atomicAdd(&g_nsum[c], (double)s);
        atomicAdd(&g_nsq[c], (double)q);
    }
}

// ---------------- node-BN scale/shift prep -----------------------------------
__global__ void k_bnprep_n(const float* __restrict__ gn, const float* __restrict__ bnb, int Nn) {
    int c = threadIdx.x;
    if (c < D) {
        double mn = g_nsum[c] / (double)Nn;
        double vn = g_nsq[c] / (double)Nn - mn * mn;
        double rsn = 1.0 / sqrt(vn + 1e-5);
        g_bna[c] = (float)(rsn)*gn[c];
        g_bnb[c] = bnb[c] - (float)(mn * rsn) * gn[c];
    }
}

// ---------------- finalize x ------------------------------------------------
__global__ void k_xout(const float* __restrict__ node, float* __restrict__ out, int Nn) {
    int i = blockIdx.x * blockDim.x + threadIdx.x;
    if (i >= Nn * 16) return;
    int c4 = (i & 15) * 4;
    float4 xp = *(const float4*)&g_xpre[(size_t)i * 4];
    float4 nf = ((const float4*)node)[i];
    float v[4] = {xp.x, xp.y, xp.z, xp.w};
    float nn[4] = {nf.x, nf.y, nf.z, nf.w};
    float o[4];
    #pragma unroll
    for (int j = 0; j < 4; j++) {
        float t = fmaf(v[j], g_bna[c4 + j], g_bnb[c4 + j]);
        o[j] = nn[j] + t / (1.f + expf(-t));
    }
    ((float4*)out)[i] = make_float4(o[0], o[1], o[2], o[3]);
}

// ---------------- host ------------------------------------------------------
extern "C" void kernel_launch(void* const* d_in, const int* in_sizes, int n_in,
                              void* d_out, int out_size) {
    const float* node = (const float*)d_in[0];
    const float* edge = (const float*)d_in[1];
    const int* src = (const int*)d_in[2];
    const int* dst = (const int*)d_in[3];
    const float* Wsg = (const float*)d_in[4];
    const float* bsg = (const float*)d_in[5];
    const float* Wdg = (const float*)d_in[6];
    const float* bdg = (const float*)d_in[7];
    const float* Weg = (const float*)d_in[8];
    const float* beg = (const float*)d_in[9];
    const float* Wsu = (const float*)d_in[10];
    const float* bsu = (const float*)d_in[11];
    const float* Wdu = (const float*)d_in[12];
    const float* bdu = (const float*)d_in[13];
    const float* Wgat = (const float*)d_in[14];
    const float* bgat = (const float*)d_in[15];
    const float* attl = (const float*)d_in[16];
    const float* attr = (const float*)d_in[17];
    const float* gn = (const float*)d_in[18];
    const float* bn = (const float*)d_in[19];
    const float* ge = (const float*)d_in[20];
    const float* be = (const float*)d_in[21];

    int Nn = in_sizes[0] / D;
    int E = in_sizes[2];
    float* out = (float*)d_out;
    float* yout = out + (size_t)Nn * D;

    int scanB = (Nn + 511) / 512;
    // order chosen so k_edge sits in the ncu-captured slot (4th launch)
    k_init<<<(Nn + 255) / 256, 256>>>(Nn);
    k_wcomb<<<16, 256>>>(Wsu, bsu, Wgat);
    k_node<<<(Nn + TR - 1) / TR, 256>>>(node, Wsg, bsg, Wdg, bdg, Wdu, bdu, Nn);
    k_edge<<<(E + TR - 1) / TR, 256>>>(edge, Weg, beg, src, dst, E);
    k_deg<<<(E + 255) / 256, 256>>>(dst, E);
    k_scan1<<<scanB, 512>>>(Nn);
    k_scan2<<<1, 128>>>(scanB);
    k_scan3<<<(Nn + 255) / 256, 256>>>(Nn);
    k_fill<<<(E + 255) / 256, 256>>>(dst, E);
    k_attn<<<(Nn * 32 + 255) / 256, 256>>>(attl, attr, Nn);
    k_bnprep_e<<<1, 64>>>(ge, be, E);
    k_gather<<<(Nn * 32 + 255) / 256, 256>>>(src, bgat, edge, yout, Nn);
    k_nstats<<<128, 256>>>(Nn);
    k_bnprep_n<<<1, 64>>>(gn, bn, Nn);
    k_xout<<<(Nn * 16 + 255) / 256, 256>>>(node, out, Nn);
}